// round 8
// baseline (speedup 1.0000x reference)
#include <cuda_runtime.h>
#include <math.h>

#define B 512
#define S 400
#define V 50000
#define E 512
#define H 256
#define EMB 128
#define X 640
#define KX 896
#define G4 1024

#define OFF_COV   25600000
#define OFF_HT    25804800
#define OFF_CT    25935872
#define OFF_ATTN  26066944
#define OFF_LOSS  26271744

__device__ float g_xh[B*KX];
__device__ float g_gates[B*G4];
__device__ float g_wsapp[B*H];
__device__ float g_pgen[B];
__device__ float g_energy[B*S];
__device__ float g_rmax[B];
__device__ float g_rinv[B];
__device__ float g_loss[B];
__device__ float g_logits[(size_t)B*V];
__device__ int   g_win[(size_t)B*V];

__device__ __forceinline__ float sigm(float x){ return 1.f/(1.f+expf(-x)); }

// ---- shared GEMM skeleton: 64 rows x 256 cols x K, BK=16, 256 thr, 8x8 micro ----
#define GEMM_PROLOG \
  __shared__ float As[2][16][68]; \
  __shared__ float Bs[2][16][260]; \
  const int tid=threadIdx.x, tr=tid>>5, tc=tid&31, arow=tid>>2, acg=tid&3; \
  float acc[8][8]; \
  _Pragma("unroll") for(int i=0;i<8;i++) _Pragma("unroll") for(int j=0;j<8;j++) acc[i][j]=0.f; \
  float4 aR, bR[4];

#define STORE_TILE(buf) \
  As[buf][acg*4+0][arow]=aR.x; As[buf][acg*4+1][arow]=aR.y; \
  As[buf][acg*4+2][arow]=aR.z; As[buf][acg*4+3][arow]=aR.w; \
  _Pragma("unroll") for(int i=0;i<4;i++){ int lin=i*256+tid, hh=lin>>2, cg=lin&3; \
    Bs[buf][cg*4+0][hh]=bR[i].x; Bs[buf][cg*4+1][hh]=bR[i].y; \
    Bs[buf][cg*4+2][hh]=bR[i].z; Bs[buf][cg*4+3][hh]=bR[i].w; }

#define MMA_STEP(cur) \
  _Pragma("unroll") for(int kk=0;kk<16;kk++){ \
    float4 a0=*(const float4*)&As[cur][kk][tr*8]; \
    float4 a1=*(const float4*)&As[cur][kk][tr*8+4]; \
    float4 b0=*(const float4*)&Bs[cur][kk][tc*4]; \
    float4 b1=*(const float4*)&Bs[cur][kk][128+tc*4]; \
    float aa[8]={a0.x,a0.y,a0.z,a0.w,a1.x,a1.y,a1.z,a1.w}; \
    float bb[8]={b0.x,b0.y,b0.z,b0.w,b1.x,b1.y,b1.z,b1.w}; \
    _Pragma("unroll") for(int i2=0;i2<8;i2++) \
    _Pragma("unroll") for(int j2=0;j2<8;j2++) acc[i2][j2]+=aa[i2]*bb[j2]; }

// K1: context, pack [ctx|emb|h0], p_gen partial
__global__ void k_context(const float* __restrict__ attn, const float* __restrict__ enc,
                          const float* __restrict__ emb_table, const int* __restrict__ dec,
                          const float* __restrict__ h0, const float* __restrict__ wh,
                          const float* __restrict__ wx){
  int b=blockIdx.x, t=threadIdx.x; // 512 thr, t==e
  __shared__ float sa[S]; __shared__ float red[512];
  if(t<S) sa[t]=attn[b*S+t];
  __syncthreads();
  const float* ep=enc+((size_t)b*S)*E+t;
  float a0=0,a1=0,a2=0,a3=0;
  for(int s=0;s<S;s+=4){
    a0+=sa[s  ]*ep[(size_t)(s  )*E]; a1+=sa[s+1]*ep[(size_t)(s+1)*E];
    a2+=sa[s+2]*ep[(size_t)(s+2)*E]; a3+=sa[s+3]*ep[(size_t)(s+3)*E];
  }
  float ctx=(a0+a1)+(a2+a3);
  g_xh[b*KX+t]=ctx;
  float pg=ctx*wh[t];
  if(t<EMB){ float em=emb_table[(size_t)dec[b]*EMB+t]; g_xh[b*KX+E+t]=em; pg+=em*wx[t]; }
  if(t<H) g_xh[b*KX+X+t]=h0[b*H+t];
  red[t]=pg; __syncthreads();
  for(int o=256;o;o>>=1){ if(t<o) red[t]+=red[t+o]; __syncthreads(); }
  if(t==0) g_pgen[b]=red[0];
}

// K2: gates GEMM  [512,896] x [1024,896]^T  (W_ih|W_hh fused in loader)
__global__ void __launch_bounds__(256,2) k_gates(const float* __restrict__ Wih,
                                                 const float* __restrict__ Whh,
                                                 const float* __restrict__ bih,
                                                 const float* __restrict__ bhh){
  const int j0=blockIdx.x*256, b0=blockIdx.y*64;
  GEMM_PROLOG
#define LA_G(k0) aR=*(const float4*)&g_xh[(b0+arow)*KX+(k0)+acg*4];
#define LB_G(k0) _Pragma("unroll") for(int i=0;i<4;i++){ int lin=i*256+tid,hh=lin>>2,cg=lin&3; \
    int jg=j0+hh; bR[i]=((k0)<X)?*(const float4*)&Wih[jg*X+(k0)+cg*4] \
                               :*(const float4*)&Whh[jg*H+(k0)-X+cg*4]; }
  LA_G(0) LB_G(0) STORE_TILE(0) __syncthreads();
  for(int kt=0;kt<56;kt++){ int cur=kt&1;
    if(kt+1<56){ LA_G((kt+1)*16) LB_G((kt+1)*16) }
    MMA_STEP(cur) __syncthreads();
    if(kt+1<56){ STORE_TILE(cur^1) __syncthreads(); }
  }
#pragma unroll
  for(int ssi=0;ssi<8;ssi++){ int b=b0+tr*8+ssi;
#pragma unroll
    for(int q=0;q<4;q++){
      int j=j0+tc*4+q;      g_gates[b*G4+j]=acc[ssi][q]+bih[j]+bhh[j];
      j=j0+128+tc*4+q;      g_gates[b*G4+j]=acc[ssi][4+q]+bih[j]+bhh[j];
    }
  }
}

// K3: LSTM pointwise + p_gen finalize (one b per block)
__global__ void k_lstm(const float* __restrict__ c0, const float* __restrict__ ws,
                       float* __restrict__ out){
  int b=blockIdx.x, h=threadIdx.x; // 256
  __shared__ float red[256];
  float i_=sigm(g_gates[b*G4+h]);
  float f_=sigm(g_gates[b*G4+256+h]);
  float gg=tanhf(g_gates[b*G4+512+h]);
  float o_=sigm(g_gates[b*G4+768+h]);
  float c=f_*c0[b*H+h]+i_*gg;
  float ht=o_*tanhf(c);
  out[OFF_CT+b*H+h]=c; out[OFF_HT+b*H+h]=ht;
  red[h]=ht*ws[h]; __syncthreads();
  for(int o=128;o;o>>=1){ if(h<o) red[h]+=red[h+o]; __syncthreads(); }
  if(h==0) g_pgen[b]=sigm(g_pgen[b]+red[0]);
}

// K4: ws_app = h_t @ aws_W^T + aws_b  (8 b per block)
__global__ void k_wsapp(const float* __restrict__ awsW, const float* __restrict__ awsb,
                        const float* __restrict__ out){
  int b0=blockIdx.x*8, t=threadIdx.x; // 256, t==h
  __shared__ float sht[8][H];
  const float* ht=out+OFF_HT;
  for(int i=t;i<8*H;i+=256) sht[i>>8][i&255]=ht[(b0+(i>>8))*H+(i&255)];
  __syncthreads();
  float acc[8]={0,0,0,0,0,0,0,0};
  for(int k4=0;k4<H/4;k4++){
    float4 w=*(const float4*)&awsW[t*H+k4*4];
#pragma unroll
    for(int bb=0;bb<8;bb++)
      acc[bb]+=sht[bb][k4*4]*w.x+sht[bb][k4*4+1]*w.y+sht[bb][k4*4+2]*w.z+sht[bb][k4*4+3]*w.w;
  }
  float bias=awsb[t];
#pragma unroll
  for(int bb=0;bb<8;bb++) g_wsapp[(b0+bb)*H+t]=acc[bb]+bias;
}

// K5: energy GEMM [204800,512]x[256,512]^T + tanh + dot(av)
__global__ void __launch_bounds__(256,2) k_energy(const float* __restrict__ enc,
    const float* __restrict__ awhW, const float* __restrict__ awhb,
    const float* __restrict__ awc, const float* __restrict__ av,
    const float* __restrict__ cov){
  const int r0=blockIdx.y*64;
  GEMM_PROLOG
#define LA_E(k0) aR=*(const float4*)&enc[(size_t)(r0+arow)*E+(k0)+acg*4];
#define LB_E(k0) _Pragma("unroll") for(int i=0;i<4;i++){ int lin=i*256+tid,hh=lin>>2,cg=lin&3; \
    bR[i]=*(const float4*)&awhW[hh*E+(k0)+cg*4]; }
  LA_E(0) LB_E(0) STORE_TILE(0) __syncthreads();
  for(int kt=0;kt<32;kt++){ int cur=kt&1;
    if(kt+1<32){ LA_E((kt+1)*16) LB_E((kt+1)*16) }
    MMA_STEP(cur) __syncthreads();
    if(kt+1<32){ STORE_TILE(cur^1) __syncthreads(); }
  }
  const int hA=tc*4, hB=128+tc*4;
#pragma unroll
  for(int ssi=0;ssi<8;ssi++){
    int r=r0+tr*8+ssi, b=r/S;
    float cv=cov[r], e=0.f;
#pragma unroll
    for(int q=0;q<4;q++){
      int h=hA+q;
      float z=acc[ssi][q]+awhb[h]+g_wsapp[b*H+h]+cv*awc[h];
      e+=av[h]*tanhf(z);
      h=hB+q;
      z=acc[ssi][4+q]+awhb[h]+g_wsapp[b*H+h]+cv*awc[h];
      e+=av[h]*tanhf(z);
    }
#pragma unroll
    for(int o=16;o;o>>=1) e+=__shfl_xor_sync(0xffffffffu,e,o);
    if(tc==0) g_energy[r]=e;
  }
}

// K6: attention softmax + coverage + per-b loss
__global__ void k_attnsm(const float* __restrict__ cov, float* __restrict__ out){
  int b=blockIdx.x, t=threadIdx.x; // 128
  __shared__ float se[S]; __shared__ float red[128];
  for(int i=t;i<S;i+=128) se[i]=g_energy[b*S+i];
  __syncthreads();
  float m=-1e30f;
  for(int i=t;i<S;i+=128) m=fmaxf(m,se[i]);
  red[t]=m; __syncthreads();
  for(int o=64;o;o>>=1){ if(t<o) red[t]=fmaxf(red[t],red[t+o]); __syncthreads(); }
  m=red[0]; __syncthreads();
  float s=0.f;
  for(int i=t;i<S;i+=128) s+=expf(se[i]-m);
  red[t]=s; __syncthreads();
  for(int o=64;o;o>>=1){ if(t<o) red[t]+=red[t+o]; __syncthreads(); }
  float inv=1.f/red[0]; __syncthreads();
  float lp=0.f;
  for(int i=t;i<S;i+=128){
    float a=expf(se[i]-m)*inv, cv=cov[b*S+i];
    out[OFF_ATTN+b*S+i]=a;
    out[OFF_COV+b*S+i]=cv+a;
    lp+=fminf(a,cv);
  }
  red[t]=lp; __syncthreads();
  for(int o=64;o;o>>=1){ if(t<o) red[t]+=red[t+o]; __syncthreads(); }
  if(t==0) g_loss[b]=red[0];
}

__global__ void k_lossred(float* __restrict__ out){
  int t=threadIdx.x; __shared__ float red[512];
  red[t]=g_loss[t]; __syncthreads();
  for(int o=256;o;o>>=1){ if(t<o) red[t]+=red[t+o]; __syncthreads(); }
  if(t==0) out[OFF_LOSS]=red[0];
}

// K7: vocab logits GEMM [512,256]x[50000,256]^T -> g_logits
__global__ void __launch_bounds__(256,2) k_vocab(const float* __restrict__ vW,
                                                 const float* __restrict__ vb,
                                                 const float* __restrict__ out){
  const int v0=blockIdx.x*256, b0=blockIdx.y*64;
  const float* ht=out+OFF_HT;
  GEMM_PROLOG
#define LA_V(k0) aR=*(const float4*)&ht[(b0+arow)*H+(k0)+acg*4];
#define LB_V(k0) _Pragma("unroll") for(int i=0;i<4;i++){ int lin=i*256+tid,hh=lin>>2,cg=lin&3; \
    int vg=v0+hh; bR[i]=(vg<V)?*(const float4*)&vW[(size_t)vg*H+(k0)+cg*4]:make_float4(0,0,0,0); }
  LA_V(0) LB_V(0) STORE_TILE(0) __syncthreads();
  for(int kt=0;kt<16;kt++){ int cur=kt&1;
    if(kt+1<16){ LA_V((kt+1)*16) LB_V((kt+1)*16) }
    MMA_STEP(cur) __syncthreads();
    if(kt+1<16){ STORE_TILE(cur^1) __syncthreads(); }
  }
#pragma unroll
  for(int ssi=0;ssi<8;ssi++){ int b=b0+tr*8+ssi;
#pragma unroll
    for(int q=0;q<4;q++){
      int v=v0+tc*4+q;
      if(v<V) g_logits[(size_t)b*V+v]=acc[ssi][q]+vb[v];
      v=v0+128+tc*4+q;
      if(v<V) g_logits[(size_t)b*V+v]=acc[ssi][4+q]+vb[v];
    }
  }
}

// K8: per-row max + 1/sum over vocab
__global__ void k_rowstats(){
  int b=blockIdx.x, t=threadIdx.x; // 256
  __shared__ float sm[256], ssu[256];
  float m=-1e30f, s=0.f;
  const float* row=g_logits+(size_t)b*V;
  for(int v=t;v<V;v+=256){
    float l=row[v], nm=fmaxf(m,l);
    s=s*expf(m-nm)+expf(l-nm); m=nm;
  }
  sm[t]=m; ssu[t]=s; __syncthreads();
  for(int o=128;o;o>>=1){
    if(t<o){ float m1=sm[t],m2=sm[t+o],nm=fmaxf(m1,m2);
      ssu[t]=ssu[t]*expf(m1-nm)+ssu[t+o]*expf(m2-nm); sm[t]=nm; }
    __syncthreads();
  }
  if(t==0){ g_rmax[b]=sm[0]; g_rinv[b]=1.f/ssu[0]; }
}

// K9: out = p_gen * softmax(logits)
__global__ void k_final(float* __restrict__ out){
  size_t idx=(size_t)blockIdx.x*256+threadIdx.x;
  int b=(int)(idx/V);
  out[idx]=g_pgen[b]*expf(g_logits[idx]-g_rmax[b])*g_rinv[b];
}

// K10a: reset winner slots at touched positions only
__global__ void k_scat_reset(const int* __restrict__ enc_in){
  int idx=blockIdx.x*256+threadIdx.x; // B*S
  int b=idx/S;
  g_win[(size_t)b*V+enc_in[idx]] = -1;
}

// K10b: elect winner = highest s (XLA scatter: last update wins)
__global__ void k_scat_win(const int* __restrict__ enc_in){
  int idx=blockIdx.x*256+threadIdx.x; // B*S
  int b=idx/S, s=idx-b*S;
  atomicMax(&g_win[(size_t)b*V+enc_in[idx]], s);
}

// K10c: winner writes p_gen*p_vocab + (1-p_gen)*new_attn (plain store; unique winner)
__global__ void k_scatter(const int* __restrict__ enc_in, float* __restrict__ out){
  int idx=blockIdx.x*256+threadIdx.x; // B*S
  int b=idx/S, s=idx-b*S;
  int v=enc_in[idx];
  size_t bv=(size_t)b*V+v;
  if(g_win[bv]!=s) return;
  float pg=g_pgen[b];
  float a=out[OFF_ATTN+idx];
  float base=pg*expf(g_logits[bv]-g_rmax[b])*g_rinv[b];
  out[bv]=base+(1.f-pg)*a;
}

extern "C" void kernel_launch(void* const* d_in, const int* in_sizes, int n_in,
                              void* d_out, int out_size){
  const float* coverage=(const float*)d_in[0];
  const float* enc     =(const float*)d_in[1];
  const float* h0      =(const float*)d_in[2];
  const float* c0      =(const float*)d_in[3];
  const float* attn    =(const float*)d_in[4];
  const int*   dec     =(const int*)  d_in[5];
  const int*   enc_in  =(const int*)  d_in[6];
  const float* emb     =(const float*)d_in[7];
  const float* Wih     =(const float*)d_in[8];
  const float* Whh     =(const float*)d_in[9];
  const float* bih     =(const float*)d_in[10];
  const float* bhh     =(const float*)d_in[11];
  const float* awhW    =(const float*)d_in[12];
  const float* awhb    =(const float*)d_in[13];
  const float* awsW    =(const float*)d_in[14];
  const float* awsb    =(const float*)d_in[15];
  const float* awc     =(const float*)d_in[16];
  const float* av      =(const float*)d_in[17];
  const float* wh      =(const float*)d_in[18];
  const float* ws      =(const float*)d_in[19];
  const float* wx      =(const float*)d_in[20];
  const float* vW      =(const float*)d_in[21];
  const float* vb      =(const float*)d_in[22];
  float* out=(float*)d_out;

  k_context<<<B,512>>>(attn,enc,emb,dec,h0,wh,wx);
  k_gates<<<dim3(G4/256,B/64),256>>>(Wih,Whh,bih,bhh);
  k_lstm<<<B,256>>>(c0,ws,out);
  k_wsapp<<<B/8,256>>>(awsW,awsb,out);
  k_energy<<<dim3(1,(B*S)/64),256>>>(enc,awhW,awhb,awc,av,coverage);
  k_attnsm<<<B,128>>>(coverage,out);
  k_lossred<<<1,512>>>(out);
  k_vocab<<<dim3((V+255)/256,B/64),256>>>(vW,vb,out);
  k_rowstats<<<B,256>>>();
  k_final<<<(int)(((size_t)B*V)/256),256>>>(out);
  k_scat_reset<<<(B*S)/256,256>>>(enc_in);
  k_scat_win<<<(B*S)/256,256>>>(enc_in);
  k_scatter<<<(B*S)/256,256>>>(enc_in,out);
}

// round 12
// speedup vs baseline: 1.7606x; 1.7606x over previous
#include <cuda_runtime.h>
#include <cuda_bf16.h>
#include <cstdint>
#include <math.h>

#define B 512
#define S 400
#define V 50000
#define E 512
#define H 256
#define EMB 128
#define X 640
#define KX 896
#define G4 1024

#define OFF_COV   25600000
#define OFF_HT    25804800
#define OFF_CT    25935872
#define OFF_ATTN  26066944
#define OFF_LOSS  26271744

__device__ float g_xh[B*KX];
__device__ float g_gates[B*G4];
__device__ float g_wsapp[B*H];
__device__ float g_pgen[B];
__device__ float g_epart[2*(size_t)B*S];
__device__ float g_rmax[B];
__device__ float g_rinv[B];
__device__ float g_loss[B];
__device__ float g_logits[(size_t)B*V];
__device__ int   g_win[(size_t)B*V];

__device__ __forceinline__ float sigm(float x){ return 1.f/(1.f+expf(-x)); }

// ======================= mma.sync helpers =======================
__device__ __forceinline__ uint32_t smem_u32(const void* p){
  uint32_t a; asm("{ .reg .u64 t; cvta.to.shared.u64 t,%1; cvt.u32.u64 %0,t; }":"=r"(a):"l"(p));
  return a;
}
__device__ __forceinline__ void ldsm4(uint32_t&r0,uint32_t&r1,uint32_t&r2,uint32_t&r3,uint32_t a){
  asm volatile("ldmatrix.sync.aligned.m8n8.x4.shared.b16 {%0,%1,%2,%3},[%4];"
    :"=r"(r0),"=r"(r1),"=r"(r2),"=r"(r3):"r"(a));
}
__device__ __forceinline__ void mma16816(float* c,const uint32_t* a,const uint32_t* b){
  asm volatile("mma.sync.aligned.m16n8k16.row.col.f32.bf16.bf16.f32 "
    "{%0,%1,%2,%3},{%4,%5,%6,%7},{%8,%9},{%0,%1,%2,%3};"
    :"+f"(c[0]),"+f"(c[1]),"+f"(c[2]),"+f"(c[3])
    :"r"(a[0]),"r"(a[1]),"r"(a[2]),"r"(a[3]),"r"(b[0]),"r"(b[1]));
}
__device__ __forceinline__ void cvt_pair(float x0,float x1,uint32_t&hi,uint32_t&lo){
  __nv_bfloat162 h = __floats2bfloat162_rn(x0,x1);
  float r0 = x0-__bfloat162float(h.x), r1 = x1-__bfloat162float(h.y);
  __nv_bfloat162 l = __floats2bfloat162_rn(r0,r1);
  hi = *(uint32_t*)&h; lo = *(uint32_t*)&l;
}

#define P 40                   // smem pitch in bf16 elems (80B) -> conflict-free ldmatrix
#define TILE_B (128*P*2)       // 10240 bytes per tile

// fill a 128x32 fp32 tile as hi/lo bf16 into smem; LD(row,col)->float4 (col multiple of 4)
#define FILL2(dstHi,dstLo,LD) { int row_=tid>>1, cb_=(tid&1)*16; \
  _Pragma("unroll") for(int q_=0;q_<4;q_++){ int col_=cb_+q_*4; \
    float4 vv_ = LD(row_,col_); \
    uint32_t h0_,h1_,l0_,l1_; cvt_pair(vv_.x,vv_.y,h0_,l0_); cvt_pair(vv_.z,vv_.w,h1_,l1_); \
    int off_=(row_*P+col_)*2; \
    *(uint2*)((char*)(dstHi)+off_)=make_uint2(h0_,h1_); \
    *(uint2*)((char*)(dstLo)+off_)=make_uint2(l0_,l1_); } }

// one K=32 chunk of 3-pass split-bf16 mma (warp tile 32x64)
#define MMA_CHUNK() \
  _Pragma("unroll") for(int k16=0;k16<2;k16++){ \
    uint32_t ah[2][4], al[2][4]; \
    _Pragma("unroll") for(int m_=0;m_<2;m_++){ \
      ldsm4(ah[m_][0],ah[m_][1],ah[m_][2],ah[m_][3], aHiU + m_*(16*P*2) + k16*32); \
      ldsm4(al[m_][0],al[m_][1],al[m_][2],al[m_][3], aLoU + m_*(16*P*2) + k16*32); } \
    _Pragma("unroll") for(int nn=0;nn<4;nn++){ \
      uint32_t bh[4], bl[4]; \
      ldsm4(bh[0],bh[1],bh[2],bh[3], bHiU + nn*(16*P*2) + k16*32); \
      ldsm4(bl[0],bl[1],bl[2],bl[3], bLoU + nn*(16*P*2) + k16*32); \
      _Pragma("unroll") for(int m_=0;m_<2;m_++){ \
        mma16816(acc[m_][2*nn],   ah[m_], bh+0); \
        mma16816(acc[m_][2*nn],   ah[m_], bl+0); \
        mma16816(acc[m_][2*nn],   al[m_], bh+0); \
        mma16816(acc[m_][2*nn+1], ah[m_], bh+2); \
        mma16816(acc[m_][2*nn+1], ah[m_], bl+2); \
        mma16816(acc[m_][2*nn+1], al[m_], bh+2); } } }

#define MMA_PROLOG \
  __shared__ __align__(16) char sAhi[TILE_B], sAlo[TILE_B], sBhi[TILE_B], sBlo[TILE_B]; \
  const int tid=threadIdx.x, lane=tid&31, warp=tid>>5; \
  const int wr=warp>>1, wc=warp&1, qrow=lane>>2, qcol=lane&3; \
  float acc[2][8][4]; \
  _Pragma("unroll") for(int i_=0;i_<2;i_++) _Pragma("unroll") for(int j_=0;j_<8;j_++) \
    _Pragma("unroll") for(int r_=0;r_<4;r_++) acc[i_][j_][r_]=0.f; \
  const uint32_t aHiU = smem_u32(sAhi) + (((wr*32+(lane&15))*P) + (lane>>4)*8)*2; \
  const uint32_t aLoU = smem_u32(sAlo) + (((wr*32+(lane&15))*P) + (lane>>4)*8)*2; \
  const uint32_t bHiU = smem_u32(sBhi) + (((wc*64+(lane&7)+((lane>>4)*8))*P) + ((lane>>3)&1)*8)*2; \
  const uint32_t bLoU = smem_u32(sBlo) + (((wc*64+(lane&7)+((lane>>4)*8))*P) + ((lane>>3)&1)*8)*2;

// K5: energy GEMM tile D[128 r, 128 h] + fused tanh·av partial epilogue
__global__ void __launch_bounds__(256,2) k_energy_mm(
    const float* __restrict__ enc, const float* __restrict__ awhW,
    const float* __restrict__ awhb, const float* __restrict__ awc,
    const float* __restrict__ av, const float* __restrict__ cov){
  __shared__ float red[128][2];
  const int h0g = blockIdx.x*128;
  const int r0  = blockIdx.y*128;
  MMA_PROLOG
  for(int c=0;c<16;c++){
    int kc = c*32;
    if(c) __syncthreads();
#define LDA_E(r_,c_) (*(const float4*)&enc[(size_t)(r0+(r_))*E + kc + (c_)])
#define LDB_E(r_,c_) (*(const float4*)&awhW[(size_t)(h0g+(r_))*E + kc + (c_)])
    FILL2(sAhi,sAlo,LDA_E)
    FILL2(sBhi,sBlo,LDB_E)
    __syncthreads();
    MMA_CHUNK()
  }
#pragma unroll
  for(int m=0;m<2;m++)
#pragma unroll
  for(int half=0;half<2;half++){
    int rr = wr*32+m*16+half*8+qrow;
    int r = r0+rr, b=r/S;
    float cv = cov[r], e=0.f;
#pragma unroll
    for(int n=0;n<8;n++)
#pragma unroll
    for(int cc=0;cc<2;cc++){
      int h = h0g + wc*64 + n*8 + qcol*2 + cc;
      float z = acc[m][n][half*2+cc] + awhb[h] + g_wsapp[b*H+h] + cv*awc[h];
      e = fmaf(av[h], tanhf(z), e);
    }
    e += __shfl_xor_sync(0xffffffffu,e,1);
    e += __shfl_xor_sync(0xffffffffu,e,2);
    if(qcol==0) red[rr][wc]=e;
  }
  __syncthreads();
  if(tid<128) g_epart[(size_t)blockIdx.x*(B*S) + r0 + tid] = red[tid][0]+red[tid][1];
}

// K7: vocab logits GEMM tile D[128 b, 128 v]
__global__ void __launch_bounds__(256,2) k_vocab_mm(
    const float* __restrict__ vW, const float* __restrict__ vb,
    const float* __restrict__ out){
  const int v0 = blockIdx.x*128;
  const int b0 = blockIdx.y*128;
  const float* ht = out + OFF_HT;
  MMA_PROLOG
  const float4 f4z = make_float4(0,0,0,0);
  for(int c=0;c<8;c++){
    int kc = c*32;
    if(c) __syncthreads();
#define LDA_V(r_,c_) (*(const float4*)&ht[(size_t)(b0+(r_))*H + kc + (c_)])
#define LDB_V(r_,c_) ((v0+(r_))<V ? *(const float4*)&vW[(size_t)(v0+(r_))*H + kc + (c_)] : f4z)
    FILL2(sAhi,sAlo,LDA_V)
    FILL2(sBhi,sBlo,LDB_V)
    __syncthreads();
    MMA_CHUNK()
  }
#pragma unroll
  for(int m=0;m<2;m++)
#pragma unroll
  for(int n=0;n<8;n++)
#pragma unroll
  for(int rg=0;rg<4;rg++){
    int bb = b0 + wr*32 + m*16 + (rg>>1)*8 + qrow;
    int v  = v0 + wc*64 + n*8 + qcol*2 + (rg&1);
    if(v<V) g_logits[(size_t)bb*V+v] = acc[m][n][rg] + vb[v];
  }
}

// ======================= fp32 kernels =======================
#define GEMM_PROLOG \
  __shared__ float As[2][16][68]; \
  __shared__ float Bs[2][16][260]; \
  const int tid=threadIdx.x, tr=tid>>5, tc=tid&31, arow=tid>>2, acg=tid&3; \
  float acc[8][8]; \
  _Pragma("unroll") for(int i=0;i<8;i++) _Pragma("unroll") for(int j=0;j<8;j++) acc[i][j]=0.f; \
  float4 aR, bR[4];

#define STORE_TILE(buf) \
  As[buf][acg*4+0][arow]=aR.x; As[buf][acg*4+1][arow]=aR.y; \
  As[buf][acg*4+2][arow]=aR.z; As[buf][acg*4+3][arow]=aR.w; \
  _Pragma("unroll") for(int i=0;i<4;i++){ int lin=i*256+tid, hh=lin>>2, cg=lin&3; \
    Bs[buf][cg*4+0][hh]=bR[i].x; Bs[buf][cg*4+1][hh]=bR[i].y; \
    Bs[buf][cg*4+2][hh]=bR[i].z; Bs[buf][cg*4+3][hh]=bR[i].w; }

#define MMA_STEP(cur) \
  _Pragma("unroll") for(int kk=0;kk<16;kk++){ \
    float4 a0=*(const float4*)&As[cur][kk][tr*8]; \
    float4 a1=*(const float4*)&As[cur][kk][tr*8+4]; \
    float4 b0=*(const float4*)&Bs[cur][kk][tc*4]; \
    float4 b1=*(const float4*)&Bs[cur][kk][128+tc*4]; \
    float aa[8]={a0.x,a0.y,a0.z,a0.w,a1.x,a1.y,a1.z,a1.w}; \
    float bb[8]={b0.x,b0.y,b0.z,b0.w,b1.x,b1.y,b1.z,b1.w}; \
    _Pragma("unroll") for(int i2=0;i2<8;i2++) \
    _Pragma("unroll") for(int j2=0;j2<8;j2++) acc[i2][j2]+=aa[i2]*bb[j2]; }

__global__ void k_context(const float* __restrict__ attn, const float* __restrict__ enc,
                          const float* __restrict__ emb_table, const int* __restrict__ dec,
                          const float* __restrict__ h0, const float* __restrict__ wh,
                          const float* __restrict__ wx){
  int b=blockIdx.x, t=threadIdx.x;
  __shared__ float sa[S]; __shared__ float red[512];
  if(t<S) sa[t]=attn[b*S+t];
  __syncthreads();
  const float* ep=enc+((size_t)b*S)*E+t;
  float a0=0,a1=0,a2=0,a3=0;
  for(int s=0;s<S;s+=4){
    a0+=sa[s  ]*ep[(size_t)(s  )*E]; a1+=sa[s+1]*ep[(size_t)(s+1)*E];
    a2+=sa[s+2]*ep[(size_t)(s+2)*E]; a3+=sa[s+3]*ep[(size_t)(s+3)*E];
  }
  float ctx=(a0+a1)+(a2+a3);
  g_xh[b*KX+t]=ctx;
  float pg=ctx*wh[t];
  if(t<EMB){ float em=emb_table[(size_t)dec[b]*EMB+t]; g_xh[b*KX+E+t]=em; pg+=em*wx[t]; }
  if(t<H) g_xh[b*KX+X+t]=h0[b*H+t];
  red[t]=pg; __syncthreads();
  for(int o=256;o;o>>=1){ if(t<o) red[t]+=red[t+o]; __syncthreads(); }
  if(t==0) g_pgen[b]=red[0];
}

__global__ void __launch_bounds__(256,2) k_gates(const float* __restrict__ Wih,
                                                 const float* __restrict__ Whh,
                                                 const float* __restrict__ bih,
                                                 const float* __restrict__ bhh){
  const int j0=blockIdx.x*256, b0=blockIdx.y*64;
  GEMM_PROLOG
#define LA_G(k0) aR=*(const float4*)&g_xh[(b0+arow)*KX+(k0)+acg*4];
#define LB_G(k0) _Pragma("unroll") for(int i=0;i<4;i++){ int lin=i*256+tid,hh=lin>>2,cg=lin&3; \
    int jg=j0+hh; bR[i]=((k0)<X)?*(const float4*)&Wih[jg*X+(k0)+cg*4] \
                               :*(const float4*)&Whh[jg*H+(k0)-X+cg*4]; }
  LA_G(0) LB_G(0) STORE_TILE(0) __syncthreads();
  for(int kt=0;kt<56;kt++){ int cur=kt&1;
    if(kt+1<56){ LA_G((kt+1)*16) LB_G((kt+1)*16) }
    MMA_STEP(cur) __syncthreads();
    if(kt+1<56){ STORE_TILE(cur^1) __syncthreads(); }
  }
#pragma unroll
  for(int ssi=0;ssi<8;ssi++){ int b=b0+tr*8+ssi;
#pragma unroll
    for(int q=0;q<4;q++){
      int j=j0+tc*4+q;      g_gates[b*G4+j]=acc[ssi][q]+bih[j]+bhh[j];
      j=j0+128+tc*4+q;      g_gates[b*G4+j]=acc[ssi][4+q]+bih[j]+bhh[j];
    }
  }
}

__global__ void k_lstm(const float* __restrict__ c0, const float* __restrict__ ws,
                       float* __restrict__ out){
  int b=blockIdx.x, h=threadIdx.x;
  __shared__ float red[256];
  float i_=sigm(g_gates[b*G4+h]);
  float f_=sigm(g_gates[b*G4+256+h]);
  float gg=tanhf(g_gates[b*G4+512+h]);
  float o_=sigm(g_gates[b*G4+768+h]);
  float c=f_*c0[b*H+h]+i_*gg;
  float ht=o_*tanhf(c);
  out[OFF_CT+b*H+h]=c; out[OFF_HT+b*H+h]=ht;
  red[h]=ht*ws[h]; __syncthreads();
  for(int o=128;o;o>>=1){ if(h<o) red[h]+=red[h+o]; __syncthreads(); }
  if(h==0) g_pgen[b]=sigm(g_pgen[b]+red[0]);
}

__global__ void k_wsapp(const float* __restrict__ awsW, const float* __restrict__ awsb,
                        const float* __restrict__ out){
  int b0=blockIdx.x*8, t=threadIdx.x;
  __shared__ float sht[8][H];
  const float* ht=out+OFF_HT;
  for(int i=t;i<8*H;i+=256) sht[i>>8][i&255]=ht[(b0+(i>>8))*H+(i&255)];
  __syncthreads();
  float acc[8]={0,0,0,0,0,0,0,0};
  for(int k4=0;k4<H/4;k4++){
    float4 w=*(const float4*)&awsW[t*H+k4*4];
#pragma unroll
    for(int bb=0;bb<8;bb++)
      acc[bb]+=sht[bb][k4*4]*w.x+sht[bb][k4*4+1]*w.y+sht[bb][k4*4+2]*w.z+sht[bb][k4*4+3]*w.w;
  }
  float bias=awsb[t];
#pragma unroll
  for(int bb=0;bb<8;bb++) g_wsapp[(b0+bb)*H+t]=acc[bb]+bias;
}

__global__ void k_attnsm(const float* __restrict__ cov, float* __restrict__ out){
  int b=blockIdx.x, t=threadIdx.x;
  __shared__ float se[S]; __shared__ float red[128];
  for(int i=t;i<S;i+=128) se[i]=g_epart[b*S+i]+g_epart[(size_t)B*S+b*S+i];
  __syncthreads();
  float m=-1e30f;
  for(int i=t;i<S;i+=128) m=fmaxf(m,se[i]);
  red[t]=m; __syncthreads();
  for(int o=64;o;o>>=1){ if(t<o) red[t]=fmaxf(red[t],red[t+o]); __syncthreads(); }
  m=red[0]; __syncthreads();
  float s=0.f;
  for(int i=t;i<S;i+=128) s+=expf(se[i]-m);
  red[t]=s; __syncthreads();
  for(int o=64;o;o>>=1){ if(t<o) red[t]+=red[t+o]; __syncthreads(); }
  float inv=1.f/red[0]; __syncthreads();
  float lp=0.f;
  for(int i=t;i<S;i+=128){
    float a=expf(se[i]-m)*inv, cv=cov[b*S+i];
    out[OFF_ATTN+b*S+i]=a;
    out[OFF_COV+b*S+i]=cv+a;
    lp+=fminf(a,cv);
  }
  red[t]=lp; __syncthreads();
  for(int o=64;o;o>>=1){ if(t<o) red[t]+=red[t+o]; __syncthreads(); }
  if(t==0) g_loss[b]=red[0];
}

__global__ void k_lossred(float* __restrict__ out){
  int t=threadIdx.x; __shared__ float red[512];
  red[t]=g_loss[t]; __syncthreads();
  for(int o=256;o;o>>=1){ if(t<o) red[t]+=red[t+o]; __syncthreads(); }
  if(t==0) out[OFF_LOSS]=red[0];
}

__global__ void k_rowstats(){
  int b=blockIdx.x, t=threadIdx.x;
  __shared__ float sm[256], ssu[256];
  float m=-1e30f, s=0.f;
  const float* row=g_logits+(size_t)b*V;
  for(int v=t;v<V;v+=256){
    float l=row[v], nm=fmaxf(m,l);
    s=s*expf(m-nm)+expf(l-nm); m=nm;
  }
  sm[t]=m; ssu[t]=s; __syncthreads();
  for(int o=128;o;o>>=1){
    if(t<o){ float m1=sm[t],m2=sm[t+o],nm=fmaxf(m1,m2);
      ssu[t]=ssu[t]*expf(m1-nm)+ssu[t+o]*expf(m2-nm); sm[t]=nm; }
    __syncthreads();
  }
  if(t==0){ g_rmax[b]=sm[0]; g_rinv[b]=1.f/ssu[0]; }
}

__global__ void k_final(float* __restrict__ out){
  size_t idx=(size_t)blockIdx.x*256+threadIdx.x;
  int b=(int)(idx/V);
  out[idx]=g_pgen[b]*expf(g_logits[idx]-g_rmax[b])*g_rinv[b];
}

__global__ void k_scat_reset(const int* __restrict__ enc_in){
  int idx=blockIdx.x*256+threadIdx.x;
  int b=idx/S;
  g_win[(size_t)b*V+enc_in[idx]] = -1;
}

__global__ void k_scat_win(const int* __restrict__ enc_in){
  int idx=blockIdx.x*256+threadIdx.x;
  int b=idx/S, s=idx-b*S;
  atomicMax(&g_win[(size_t)b*V+enc_in[idx]], s);
}

__global__ void k_scatter(const int* __restrict__ enc_in, float* __restrict__ out){
  int idx=blockIdx.x*256+threadIdx.x;
  int b=idx/S, s=idx-b*S;
  int v=enc_in[idx];
  size_t bv=(size_t)b*V+v;
  if(g_win[bv]!=s) return;
  float pg=g_pgen[b];
  float a=out[OFF_ATTN+idx];
  float base=pg*expf(g_logits[bv]-g_rmax[b])*g_rinv[b];
  out[bv]=base+(1.f-pg)*a;
}

extern "C" void kernel_launch(void* const* d_in, const int* in_sizes, int n_in,
                              void* d_out, int out_size){
  const float* coverage=(const float*)d_in[0];
  const float* enc     =(const float*)d_in[1];
  const float* h0      =(const float*)d_in[2];
  const float* c0      =(const float*)d_in[3];
  const float* attn    =(const float*)d_in[4];
  const int*   dec     =(const int*)  d_in[5];
  const int*   enc_in  =(const int*)  d_in[6];
  const float* emb     =(const float*)d_in[7];
  const float* Wih     =(const float*)d_in[8];
  const float* Whh     =(const float*)d_in[9];
  const float* bih     =(const float*)d_in[10];
  const float* bhh     =(const float*)d_in[11];
  const float* awhW    =(const float*)d_in[12];
  const float* awhb    =(const float*)d_in[13];
  const float* awsW    =(const float*)d_in[14];
  const float* awsb    =(const float*)d_in[15];
  const float* awc     =(const float*)d_in[16];
  const float* av      =(const float*)d_in[17];
  const float* wh      =(const float*)d_in[18];
  const float* ws      =(const float*)d_in[19];
  const float* wx      =(const float*)d_in[20];
  const float* vW      =(const float*)d_in[21];
  const float* vb      =(const float*)d_in[22];
  float* out=(float*)d_out;

  k_context<<<B,512>>>(attn,enc,emb,dec,h0,wh,wx);
  k_gates<<<dim3(G4/256,B/64),256>>>(Wih,Whh,bih,bhh);
  k_lstm<<<B,256>>>(c0,ws,out);
  k_wsapp<<<B/8,256>>>(awsW,awsb,out);
  k_energy_mm<<<dim3(2,(B*S)/128),256>>>(enc,awhW,awhb,awc,av,coverage);
  k_attnsm<<<B,128>>>(coverage,out);
  k_lossred<<<1,512>>>(out);
  k_vocab_mm<<<dim3((V+127)/128,B/128),256>>>(vW,vb,out);
  k_rowstats<<<B,256>>>();
  k_final<<<(int)(((size_t)B*V)/256),256>>>(out);
  k_scat_reset<<<(B*S)/256,256>>>(enc_in);
  k_scat_win<<<(B*S)/256,256>>>(enc_in);
  k_scatter<<<(B*S)/256,256>>>(enc_in,out);
}